// round 1
// baseline (speedup 1.0000x reference)
#include <cuda_runtime.h>
#include <math.h>

#define BQ 32
#define BP 256
#define NB 288
#define L 16
#define CIN 8192
#define H1 256
#define H2 32
#define NW (CIN/32)   // 256 mask words per row

// ---------------- scratch (device globals; no allocation) ----------------
__device__ float    g_encT[CIN*H1];         // enc_w transposed: [c][f]
__device__ float    g_cwT[3][H1*5*H1];      // conv weights as [i][k][o]
__device__ float    g_w1T[2*H1*H2];         // dec_w1 transposed [i][j]
__device__ float    g_w2T[H2*H2];           // dec_w2 transposed [m][j]
__device__ float    g_xe[NB*L*H1];          // encoder output (residual source)
__device__ float    g_bufA[NB*L*H1];
__device__ float    g_bufB[NB*L*H1];
__device__ unsigned g_mask[NB*NW];          // bloom bitmasks
__device__ float    g_qbits[BQ];
__device__ float    g_emb[NB*H1];
__device__ float    g_h3[BQ*BP*H2];
__device__ float    g_desc[BQ*BP];

// ---------------- prep kernels ----------------
__global__ void k_zero_mask() {
    int i = blockIdx.x * 256 + threadIdx.x;
    if (i < NB * NW) g_mask[i] = 0u;
}

// dst[c*R + r] = src[r*C + c]
__global__ void k_transpose(const float* __restrict__ src, float* __restrict__ dst,
                            int R, int C) {
    __shared__ float tile[32][33];
    int c0 = blockIdx.x * 32, r0 = blockIdx.y * 32;
    int c = c0 + threadIdx.x;
    for (int dr = threadIdx.y; dr < 32; dr += blockDim.y) {
        int r = r0 + dr;
        tile[dr][threadIdx.x] = (r < R && c < C) ? src[r * C + c] : 0.f;
    }
    __syncthreads();
    int r = r0 + threadIdx.x;
    for (int dc = threadIdx.y; dc < 32; dc += blockDim.y) {
        int cc = c0 + dc;
        if (cc < C && r < R) dst[cc * R + r] = tile[threadIdx.x][dc];
    }
}

// conv weights (O,I,K) -> (I,K,O)
__global__ void k_cw_reshape(const float* __restrict__ src, float* __restrict__ dst) {
    int idx = blockIdx.x * 256 + threadIdx.x;
    if (idx >= H1 * 5 * H1) return;
    int o = idx & 255;
    int k = (idx >> 8) % 5;
    int i = idx / 1280;
    dst[idx] = src[o * 1280 + i * 5 + k];
}

// ---------------- encode + bloom (sparse, deterministic) ----------------
#define NZCAP 2048
__global__ void k_encode(const float* __restrict__ qx, const float* __restrict__ px) {
    __shared__ unsigned short sidx[NZCAP];
    __shared__ int scan[256];
    int r = blockIdx.x, l = blockIdx.y, t = threadIdx.x;
    const float* x = (r < BQ) ? (qx + (size_t)(r * L + l) * CIN)
                              : (px + (size_t)((r - BQ) * L + l) * CIN);
    const float4* x4 = (const float4*)(x + t * 32);
    int cnt = 0;
    unsigned mword = 0;
#pragma unroll
    for (int j = 0; j < 8; j++) {
        float4 v = x4[j];
        if (v.x != 0.f) { cnt++; mword |= 1u << (j * 4 + 0); }
        if (v.y != 0.f) { cnt++; mword |= 1u << (j * 4 + 1); }
        if (v.z != 0.f) { cnt++; mword |= 1u << (j * 4 + 2); }
        if (v.w != 0.f) { cnt++; mword |= 1u << (j * 4 + 3); }
    }
    if (mword) atomicOr(&g_mask[r * NW + t], mword);  // OR: order-independent
    scan[t] = cnt;
    __syncthreads();
    for (int off = 1; off < 256; off <<= 1) {
        int v = 0;
        if (t >= off) v = scan[t - off];
        __syncthreads();
        scan[t] += v;
        __syncthreads();
    }
    int total = scan[255];
    if (total > NZCAP) total = NZCAP;
    int base = scan[t] - cnt;
    unsigned m = mword;
    while (m && base < NZCAP) {
        int b = __ffs(m) - 1;
        m &= m - 1;
        sidx[base++] = (unsigned short)(t * 32 + b);
    }
    __syncthreads();
    float acc = 0.f;
    for (int j = 0; j < total; j++)
        acc += g_encT[(int)sidx[j] * H1 + t];
    g_xe[(size_t)(r * L + l) * H1 + t] = acc;
}

__global__ void k_qbits() {
    __shared__ int red[256];
    int q = blockIdx.x, t = threadIdx.x;
    red[t] = __popc(g_mask[q * NW + t]);
    __syncthreads();
    for (int s = 128; s > 0; s >>= 1) {
        if (t < s) red[t] += red[t + s];
        __syncthreads();
    }
    if (t == 0) g_qbits[q] = (float)red[0];
}

// ---------------- conv layer (2 batches / block) ----------------
__global__ void k_conv(const float* __restrict__ hin, const float* __restrict__ cwT,
                       const float* __restrict__ bias, float* __restrict__ hout) {
    __shared__ float sh[2][256 * 21];  // [i][l+2], padded 20->21 (bank-conflict free)
    int o = threadIdx.x;
    int b0 = blockIdx.x * 2;
#pragma unroll
    for (int g = 0; g < 2; g++) {
        sh[g][o * 21 + 0] = 0.f; sh[g][o * 21 + 1] = 0.f;
        sh[g][o * 21 + 18] = 0.f; sh[g][o * 21 + 19] = 0.f;
    }
#pragma unroll
    for (int g = 0; g < 2; g++) {
        const float* src = hin + (size_t)(b0 + g) * (L * H1);
#pragma unroll
        for (int tt = 0; tt < 16; tt++) {
            int t = tt * 256 + o;
            int ll = t >> 8, ii = t & 255;
            sh[g][ii * 21 + ll + 2] = src[t];
        }
    }
    __syncthreads();
    float bo = bias[o];
    float acc0[16], acc1[16];
#pragma unroll
    for (int l = 0; l < 16; l++) { acc0[l] = bo; acc1[l] = bo; }
    for (int i = 0; i < 256; i++) {
        const float* wrow = cwT + i * 1280 + o;
        float w0 = wrow[0], w1 = wrow[256], w2 = wrow[512], w3 = wrow[768], w4 = wrow[1024];
        {
            float hv[20];
#pragma unroll
            for (int j = 0; j < 20; j++) hv[j] = sh[0][i * 21 + j];
#pragma unroll
            for (int l = 0; l < 16; l++)
                acc0[l] += w0 * hv[l] + w1 * hv[l + 1] + w2 * hv[l + 2] + w3 * hv[l + 3] + w4 * hv[l + 4];
        }
        {
            float hv[20];
#pragma unroll
            for (int j = 0; j < 20; j++) hv[j] = sh[1][i * 21 + j];
#pragma unroll
            for (int l = 0; l < 16; l++)
                acc1[l] += w0 * hv[l] + w1 * hv[l + 1] + w2 * hv[l + 2] + w3 * hv[l + 3] + w4 * hv[l + 4];
        }
    }
#pragma unroll
    for (int l = 0; l < 16; l++) {
        hout[(size_t)(b0 + 0) * (L * H1) + l * 256 + o] = fmaxf(acc0[l], 0.f);
        hout[(size_t)(b0 + 1) * (L * H1) + l * 256 + o] = fmaxf(acc1[l], 0.f);
    }
}

// ---------------- mean over tokens (+ residual) ----------------
__global__ void k_emb(const float* __restrict__ hconv) {
    int r = blockIdx.x, f = threadIdx.x;
    float acc = 0.f;
#pragma unroll
    for (int l = 0; l < 16; l++)
        acc += hconv[(size_t)(r * L + l) * H1 + f] + g_xe[(size_t)(r * L + l) * H1 + f];
    g_emb[r * H1 + f] = acc * (1.f / 16.f);
}

// ---------------- pairwise decode MLP (to h3), one warp per pair ----------------
__global__ void k_pair(const float* __restrict__ b1, const float* __restrict__ b2) {
    int gw = blockIdx.x * 8 + (threadIdx.x >> 5);
    int j = threadIdx.x & 31;
    int q = gw >> 8, p = gw & 255;
    const float* qe = g_emb + q * H1;
    const float* pe = g_emb + (BQ + p) * H1;
    float acc = b1[j];
#pragma unroll 4
    for (int i = 0; i < 256; i++) acc += fmaxf(qe[i], 0.f) * g_w1T[i * 32 + j];
#pragma unroll 4
    for (int i = 0; i < 256; i++) acc += fmaxf(pe[i], 0.f) * g_w1T[(256 + i) * 32 + j];
    float h2 = fmaxf(acc, 0.f);
    float acc3 = b2[j];
#pragma unroll
    for (int m = 0; m < 32; m++) {
        float hm = __shfl_sync(0xffffffffu, h2, m);
        acc3 += hm * g_w2T[m * 32 + j];
    }
    g_h3[gw * 32 + j] = fmaxf(acc3, 0.f);
}

// ---------------- sparse decode: desc_sim via mask intersection ----------------
__global__ void k_desc(const float* __restrict__ w3) {
    __shared__ unsigned qm[NW];
    int q = blockIdx.y, pg = blockIdx.x;
    int t = threadIdx.x, lane = t & 31, wid = t >> 5;
    qm[t] = g_mask[q * NW + t];
    __syncthreads();
    int p = pg * 8 + wid;
    const float* h3r = g_h3 + (size_t)(q * 256 + p) * 32;
    float hj[32];
#pragma unroll
    for (int j = 0; j < 32; j++) hj[j] = h3r[j];
    const unsigned* pm = g_mask + (size_t)(BQ + p) * NW;
    float s = 0.f;
    int cnt = 0;
    for (int w8 = 0; w8 < 8; w8++) {
        int wi = w8 * 32 + lane;
        unsigned m = qm[wi] & pm[wi];
        cnt += __popc(m);
        while (m) {
            int b = __ffs(m) - 1;
            m &= m - 1;
            int c = wi * 32 + b;
            const float4* r4 = (const float4*)(w3 + (size_t)c * 32);
            float wv = 0.f;
#pragma unroll
            for (int j4 = 0; j4 < 8; j4++) {
                float4 v = r4[j4];
                wv += hj[j4 * 4] * v.x + hj[j4 * 4 + 1] * v.y + hj[j4 * 4 + 2] * v.z + hj[j4 * 4 + 3] * v.w;
            }
            s += (wv >= 0.f) ? wv : wv * 0.125f;
        }
    }
#pragma unroll
    for (int off = 16; off; off >>= 1) {
        s += __shfl_down_sync(0xffffffffu, s, off);
        cnt += __shfl_down_sync(0xffffffffu, cnt, off);
    }
    if (lane == 0) g_desc[q * 256 + p] = ((float)cnt + s) / g_qbits[q];
}

// ---------------- normalization + geo fusion ----------------
__global__ void k_final(const float* __restrict__ qloc, const float* __restrict__ ploc,
                        const float* __restrict__ pa, const float* __restrict__ pb,
                        const float* __restrict__ pc, const float* __restrict__ pd,
                        float* __restrict__ out) {
    __shared__ float red[256];
    int q = blockIdx.x, p = threadIdx.x;
    float ds = g_desc[q * 256 + p];
    red[p] = ds;
    __syncthreads();
    for (int s = 128; s > 0; s >>= 1) {
        if (p < s) red[p] += red[p + s];
        __syncthreads();
    }
    float mean = red[0] / 256.f;
    __syncthreads();
    float df = ds - mean;
    red[p] = df * df;
    __syncthreads();
    for (int s = 128; s > 0; s >>= 1) {
        if (p < s) red[p] += red[p + s];
        __syncthreads();
    }
    float stddev = sqrtf(red[0] / 255.f);  // ddof=1
    float dsn = df / (stddev + 1e-6f);
    float dx = qloc[q * 2] - ploc[p * 2];
    float dy = qloc[q * 2 + 1] - ploc[p * 2 + 1];
    float dist = sqrtf(dx * dx + dy * dy);
    float A = *pa, B = *pb, C = *pc, D = *pd;
    float sig = 1.f / (1.f + expf(-(A * dsn + B)));
    out[q * 256 + p] = (C - sig) * (-logf(dist + 1.f) - D);
}

// ---------------- launch ----------------
extern "C" void kernel_launch(void* const* d_in, const int* in_sizes, int n_in,
                              void* d_out, int out_size) {
    const float* query_x  = (const float*)d_in[0];
    const float* query_loc = (const float*)d_in[1];
    const float* poi_x    = (const float*)d_in[2];
    const float* poi_loc  = (const float*)d_in[3];
    const float* enc_w    = (const float*)d_in[4];
    const float* cw1 = (const float*)d_in[5];  const float* cb1 = (const float*)d_in[6];
    const float* cw2 = (const float*)d_in[7];  const float* cb2 = (const float*)d_in[8];
    const float* cw3 = (const float*)d_in[9];  const float* cb3 = (const float*)d_in[10];
    const float* dw1 = (const float*)d_in[11]; const float* db1 = (const float*)d_in[12];
    const float* dw2 = (const float*)d_in[13]; const float* db2 = (const float*)d_in[14];
    const float* dw3 = (const float*)d_in[15];
    const float* pa = (const float*)d_in[16];
    const float* pb = (const float*)d_in[17];
    const float* pc = (const float*)d_in[18];
    const float* pd = (const float*)d_in[19];
    float* out = (float*)d_out;

    float *p_encT, *p_cwT, *p_w1T, *p_w2T, *p_xe, *p_A, *p_B;
    cudaGetSymbolAddress((void**)&p_encT, g_encT);
    cudaGetSymbolAddress((void**)&p_cwT, g_cwT);
    cudaGetSymbolAddress((void**)&p_w1T, g_w1T);
    cudaGetSymbolAddress((void**)&p_w2T, g_w2T);
    cudaGetSymbolAddress((void**)&p_xe, g_xe);
    cudaGetSymbolAddress((void**)&p_A, g_bufA);
    cudaGetSymbolAddress((void**)&p_B, g_bufB);

    // prep
    k_zero_mask<<<(NB * NW + 255) / 256, 256>>>();
    k_transpose<<<dim3(CIN / 32, H1 / 32), dim3(32, 8)>>>(enc_w, p_encT, H1, CIN);
    k_cw_reshape<<<(H1 * 5 * H1 + 255) / 256, 256>>>(cw1, p_cwT + 0 * H1 * 5 * H1);
    k_cw_reshape<<<(H1 * 5 * H1 + 255) / 256, 256>>>(cw2, p_cwT + 1 * H1 * 5 * H1);
    k_cw_reshape<<<(H1 * 5 * H1 + 255) / 256, 256>>>(cw3, p_cwT + 2 * H1 * 5 * H1);
    k_transpose<<<dim3(512 / 32, 1), dim3(32, 8)>>>(dw1, p_w1T, 32, 512);
    k_transpose<<<dim3(1, 1), dim3(32, 8)>>>(dw2, p_w2T, 32, 32);

    // encode + bloom
    k_encode<<<dim3(NB, L), 256>>>(query_x, poi_x);
    k_qbits<<<BQ, 256>>>();

    // conv stack
    k_conv<<<NB / 2, 256>>>(p_xe, p_cwT + 0 * H1 * 5 * H1, cb1, p_A);
    k_conv<<<NB / 2, 256>>>(p_A, p_cwT + 1 * H1 * 5 * H1, cb2, p_B);
    k_conv<<<NB / 2, 256>>>(p_B, p_cwT + 2 * H1 * 5 * H1, cb3, p_A);
    k_emb<<<NB, 256>>>(p_A);

    // pairwise decode
    k_pair<<<BQ * BP / 8, 256>>>(db1, db2);
    k_desc<<<dim3(32, 32), 256>>>(dw3);
    k_final<<<BQ, 256>>>(query_loc, poi_loc, pa, pb, pc, pd, out);
}

// round 4
// speedup vs baseline: 2.3182x; 2.3182x over previous
#include <cuda_runtime.h>
#include <cuda_fp16.h>
#include <math.h>
#include <stdint.h>

#define BQ 32
#define BP 256
#define NB 288
#define L 16
#define LP 20          // padded token length (2 zeros each side)
#define CIN 8192
#define H1 256
#define H2 32
#define NW (CIN/32)
#define KTOT 1280      // conv GEMM K = 5*256
#define NCHK 40        // K chunks of 32

// ================= scratch (device globals) =================
__device__ float    g_encT[CIN*H1];
__device__ __half   g_wH[3*H1*KTOT];   // per layer: chunk-major [c][o][32]
__device__ __half   g_wL[3*H1*KTOT];
__device__ float    g_w1T[2*H1*H2];
__device__ float    g_w2T[H2*H2];
__device__ float    g_xe[NB*L*H1];
__device__ __half   g_hAH[NB*LP*H1];
__device__ __half   g_hAL[NB*LP*H1];
__device__ __half   g_hBH[NB*LP*H1];
__device__ __half   g_hBL[NB*LP*H1];
__device__ float    g_out3[NB*L*H1];
__device__ unsigned g_mask[NB*NW];
__device__ float    g_qbits[BQ];
__device__ float    g_emb[NB*H1];
__device__ float    g_h3[BQ*BP*H2];
__device__ float    g_desc[BQ*BP];

// ================= prep =================
__global__ void k_prep1(const float* __restrict__ dw1, const float* __restrict__ dw2) {
    int i = blockIdx.x * 256 + threadIdx.x;
    if (i < NB * NW) g_mask[i] = 0u;
    ((unsigned*)g_hAH)[i] = 0u;
    ((unsigned*)g_hAL)[i] = 0u;
    ((unsigned*)g_hBH)[i] = 0u;
    ((unsigned*)g_hBL)[i] = 0u;
    if (i < 512 * 32) { int r = i >> 5, j = i & 31; g_w1T[i] = dw1[j * 512 + r]; }
    if (i < 32 * 32)  { int m = i >> 5, j = i & 31; g_w2T[i] = dw2[j * 32 + m]; }
}

// conv weights (O,I,5) fp32 -> hi/lo fp16, chunk-major [c][o][32], k = dl*256+i
__global__ void k_prep2(const float* __restrict__ cw1, const float* __restrict__ cw2,
                        const float* __restrict__ cw3) {
    int idx = blockIdx.x * 256 + threadIdx.x;
    if (idx >= 3 * H1 * KTOT) return;
    int layer = idx / (H1 * KTOT);
    int r = idx - layer * (H1 * KTOT);
    int o = r / KTOT, k = r - o * KTOT;
    int dl = k >> 8, i = k & 255;
    const float* src = (layer == 0) ? cw1 : (layer == 1) ? cw2 : cw3;
    float v = src[o * 1280 + i * 5 + dl];
    __half h = __float2half_rn(v);
    int c = k >> 5, w = k & 31;
    size_t dst = (size_t)layer * (H1 * KTOT) + (size_t)c * (H1 * 32) + o * 32 + w;
    g_wH[dst] = h;
    g_wL[dst] = __float2half_rn(v - __half2float(h));
}

// enc_w [H1][CIN] -> encT [CIN][H1]
__global__ void k_transpose(const float* __restrict__ src, float* __restrict__ dst,
                            int R, int C) {
    __shared__ float tile[32][33];
    int c0 = blockIdx.x * 32, r0 = blockIdx.y * 32;
    int c = c0 + threadIdx.x;
    for (int dr = threadIdx.y; dr < 32; dr += blockDim.y) {
        int r = r0 + dr;
        tile[dr][threadIdx.x] = (r < R && c < C) ? src[r * C + c] : 0.f;
    }
    __syncthreads();
    int r = r0 + threadIdx.x;
    for (int dc = threadIdx.y; dc < 32; dc += blockDim.y) {
        int cc = c0 + dc;
        if (cc < C && r < R) dst[cc * R + r] = tile[threadIdx.x][dc];
    }
}

// ================= encode + bloom =================
#define NZCAP 2048
__global__ void k_encode(const float* __restrict__ qx, const float* __restrict__ px) {
    __shared__ unsigned short sidx[NZCAP];
    __shared__ int scan[256];
    int r = blockIdx.x, l = blockIdx.y, t = threadIdx.x;
    const float* x = (r < BQ) ? (qx + (size_t)(r * L + l) * CIN)
                              : (px + (size_t)((r - BQ) * L + l) * CIN);
    const float4* x4 = (const float4*)(x + t * 32);
    int cnt = 0;
    unsigned mword = 0;
#pragma unroll
    for (int j = 0; j < 8; j++) {
        float4 v = x4[j];
        if (v.x != 0.f) { cnt++; mword |= 1u << (j * 4 + 0); }
        if (v.y != 0.f) { cnt++; mword |= 1u << (j * 4 + 1); }
        if (v.z != 0.f) { cnt++; mword |= 1u << (j * 4 + 2); }
        if (v.w != 0.f) { cnt++; mword |= 1u << (j * 4 + 3); }
    }
    if (mword) atomicOr(&g_mask[r * NW + t], mword);
    scan[t] = cnt;
    __syncthreads();
    for (int off = 1; off < 256; off <<= 1) {
        int v = 0;
        if (t >= off) v = scan[t - off];
        __syncthreads();
        scan[t] += v;
        __syncthreads();
    }
    int total = scan[255];
    if (total > NZCAP) total = NZCAP;
    int base = scan[t] - cnt;
    unsigned m = mword;
    while (m && base < NZCAP) {
        int b = __ffs(m) - 1;
        m &= m - 1;
        sidx[base++] = (unsigned short)(t * 32 + b);
    }
    __syncthreads();
    float acc = 0.f;
    for (int j = 0; j < total; j++)
        acc += g_encT[(int)sidx[j] * H1 + t];
    g_xe[(size_t)(r * L + l) * H1 + t] = acc;
    __half hh = __float2half_rn(acc);
    size_t po = ((size_t)r * LP + (l + 2)) * H1 + t;
    g_hAH[po] = hh;
    g_hAL[po] = __float2half_rn(acc - __half2float(hh));
}

__global__ void k_qbits() {
    __shared__ int red[256];
    int q = blockIdx.x, t = threadIdx.x;
    red[t] = __popc(g_mask[q * NW + t]);
    __syncthreads();
    for (int s = 128; s > 0; s >>= 1) {
        if (t < s) red[t] += red[t + s];
        __syncthreads();
    }
    if (t == 0) g_qbits[q] = (float)red[0];
}

// ================= conv via mma.sync fp16 split-precision GEMM =================
// CTA: M=64 rows (4 samples x 16 tokens), N=128 outputs; 8 warps = 2(M) x 4(N),
// warp tile 32x32; K=1280 chunked by 32, double-buffered SMEM, 80B-pitch rows.
// 3-term compensation: C += Ah*Wh + Ah*Wl + Al*Wh  (fp32 accumulators).
#define SBUF  15360   // halves per chunk buffer
#define AHOF  0
#define ALOF  2560
#define BHOF  5120
#define BLOF  10240
#define CONV_SMEM (2*SBUF*2 + 512)   // 61440 B bufs + 128 floats bias

__device__ __forceinline__ void mma16816(float* c, const unsigned* a,
                                         unsigned b0, unsigned b1) {
    asm volatile(
        "mma.sync.aligned.m16n8k16.row.col.f32.f16.f16.f32 "
        "{%0,%1,%2,%3}, {%4,%5,%6,%7}, {%8,%9}, {%0,%1,%2,%3};"
        : "+f"(c[0]), "+f"(c[1]), "+f"(c[2]), "+f"(c[3])
        : "r"(a[0]), "r"(a[1]), "r"(a[2]), "r"(a[3]), "r"(b0), "r"(b1));
}

__global__ void __launch_bounds__(256) k_conv_mma(
    const __half* __restrict__ inH, const __half* __restrict__ inL,
    const __half* __restrict__ wH, const __half* __restrict__ wL,
    const float* __restrict__ bias,
    __half* __restrict__ outH, __half* __restrict__ outL,
    float* __restrict__ outF) {
    extern __shared__ __half sm[];
    float* sbias = (float*)(sm + 2 * SBUF);   // byte 61440 (FIX: was 4*SBUF = OOB)
    int tid = threadIdx.x;
    int wid = tid >> 5, lane = tid & 31;
    int wm = wid >> 2, wn = wid & 3;
    int g = lane >> 2, tg = lane & 3;
    int R0 = blockIdx.x * 64;
    int N0 = blockIdx.y * 128;

    if (tid < 128) sbias[tid] = bias[N0 + tid];

    // staging registers
    uint4 ra_h, ra_l, rb_h0, rb_h1, rb_l0, rb_l1;
    int arow = tid >> 2, aseg = tid & 3;

    auto stage_load = [&](int c) {
        int dl = c >> 3, i0 = (c & 7) * 32;
        int grow = R0 + arow;
        int s = grow >> 4, l = grow & 15;
        size_t ga = ((size_t)s * LP + l + dl) * H1 + i0 + aseg * 8;
        ra_h = *(const uint4*)(inH + ga);
        ra_l = *(const uint4*)(inL + ga);
        size_t gb = (size_t)c * (H1 * 32) + (size_t)N0 * 32 + tid * 8;
        rb_h0 = *(const uint4*)(wH + gb);
        rb_h1 = *(const uint4*)(wH + gb + 2048);
        rb_l0 = *(const uint4*)(wL + gb);
        rb_l1 = *(const uint4*)(wL + gb + 2048);
    };
    auto stage_store = [&](int c) {
        __half* buf = sm + (c & 1) * SBUF;
        *(uint4*)(buf + AHOF + arow * 40 + aseg * 8) = ra_h;
        *(uint4*)(buf + ALOF + arow * 40 + aseg * 8) = ra_l;
        *(uint4*)(buf + BHOF + arow * 40 + aseg * 8) = rb_h0;
        *(uint4*)(buf + BHOF + (arow + 64) * 40 + aseg * 8) = rb_h1;
        *(uint4*)(buf + BLOF + arow * 40 + aseg * 8) = rb_l0;
        *(uint4*)(buf + BLOF + (arow + 64) * 40 + aseg * 8) = rb_l1;
    };

    float C[2][4][4];
#pragma unroll
    for (int mt = 0; mt < 2; mt++)
#pragma unroll
        for (int nt = 0; nt < 4; nt++)
#pragma unroll
            for (int j = 0; j < 4; j++) C[mt][nt][j] = 0.f;

    stage_load(0);
    stage_store(0);
    __syncthreads();

    for (int c = 0; c < NCHK; c++) {
        if (c + 1 < NCHK) stage_load(c + 1);
        const __half* buf = sm + (c & 1) * SBUF;
#pragma unroll
        for (int kk = 0; kk < 2; kk++) {
            int c0 = kk * 16 + tg * 2;
            unsigned ah[2][4], al[2][4];
#pragma unroll
            for (int mt = 0; mt < 2; mt++) {
                int rb = wm * 32 + mt * 16 + g;
                const __half* pH = buf + AHOF;
                const __half* pL = buf + ALOF;
                ah[mt][0] = *(const unsigned*)(pH + rb * 40 + c0);
                ah[mt][1] = *(const unsigned*)(pH + (rb + 8) * 40 + c0);
                ah[mt][2] = *(const unsigned*)(pH + rb * 40 + c0 + 8);
                ah[mt][3] = *(const unsigned*)(pH + (rb + 8) * 40 + c0 + 8);
                al[mt][0] = *(const unsigned*)(pL + rb * 40 + c0);
                al[mt][1] = *(const unsigned*)(pL + (rb + 8) * 40 + c0);
                al[mt][2] = *(const unsigned*)(pL + rb * 40 + c0 + 8);
                al[mt][3] = *(const unsigned*)(pL + (rb + 8) * 40 + c0 + 8);
            }
            unsigned bh[4][2], bl[4][2];
#pragma unroll
            for (int nt = 0; nt < 4; nt++) {
                int orow = wn * 32 + nt * 8 + g;
                bh[nt][0] = *(const unsigned*)(buf + BHOF + orow * 40 + c0);
                bh[nt][1] = *(const unsigned*)(buf + BHOF + orow * 40 + c0 + 8);
                bl[nt][0] = *(const unsigned*)(buf + BLOF + orow * 40 + c0);
                bl[nt][1] = *(const unsigned*)(buf + BLOF + orow * 40 + c0 + 8);
            }
#pragma unroll
            for (int mt = 0; mt < 2; mt++)
#pragma unroll
                for (int nt = 0; nt < 4; nt++) {
                    mma16816(C[mt][nt], ah[mt], bh[nt][0], bh[nt][1]);
                    mma16816(C[mt][nt], ah[mt], bl[nt][0], bl[nt][1]);
                    mma16816(C[mt][nt], al[mt], bh[nt][0], bh[nt][1]);
                }
        }
        if (c + 1 < NCHK) stage_store(c + 1);
        __syncthreads();
    }

    // epilogue: bias + relu, write hi/lo halves (padded) or fp32 (last layer)
#pragma unroll
    for (int mt = 0; mt < 2; mt++) {
        int row0 = R0 + wm * 32 + mt * 16 + g;
#pragma unroll
        for (int nt = 0; nt < 4; nt++) {
            int lc = wn * 32 + nt * 8 + tg * 2;
            int col = N0 + lc;
            float b0v = sbias[lc], b1v = sbias[lc + 1];
            float v00 = fmaxf(C[mt][nt][0] + b0v, 0.f);
            float v01 = fmaxf(C[mt][nt][1] + b1v, 0.f);
            float v10 = fmaxf(C[mt][nt][2] + b0v, 0.f);
            float v11 = fmaxf(C[mt][nt][3] + b1v, 0.f);
            int s0 = row0 >> 4, l0 = row0 & 15;
            int s1 = (row0 + 8) >> 4, l1 = (row0 + 8) & 15;
            if (outF) {
                *(float2*)(outF + ((size_t)s0 * L + l0) * H1 + col) = make_float2(v00, v01);
                *(float2*)(outF + ((size_t)s1 * L + l1) * H1 + col) = make_float2(v10, v11);
            } else {
                size_t o0 = ((size_t)s0 * LP + l0 + 2) * H1 + col;
                size_t o1 = ((size_t)s1 * LP + l1 + 2) * H1 + col;
                __half h00 = __float2half_rn(v00);
                __half h01 = __float2half_rn(v01);
                __half h10 = __float2half_rn(v10);
                __half h11 = __float2half_rn(v11);
                *(__half2*)(outH + o0) = __halves2half2(h00, h01);
                *(__half2*)(outH + o1) = __halves2half2(h10, h11);
                *(__half2*)(outL + o0) = __halves2half2(
                    __float2half_rn(v00 - __half2float(h00)),
                    __float2half_rn(v01 - __half2float(h01)));
                *(__half2*)(outL + o1) = __halves2half2(
                    __float2half_rn(v10 - __half2float(h10)),
                    __float2half_rn(v11 - __half2float(h11)));
            }
        }
    }
}

// ================= mean over tokens (+ residual) =================
__global__ void k_emb() {
    int r = blockIdx.x, f = threadIdx.x;
    float acc = 0.f;
#pragma unroll
    for (int l = 0; l < 16; l++)
        acc += g_out3[(size_t)(r * L + l) * H1 + f] + g_xe[(size_t)(r * L + l) * H1 + f];
    g_emb[r * H1 + f] = acc * (1.f / 16.f);
}

// ================= pairwise decode MLP =================
__global__ void k_pair(const float* __restrict__ b1, const float* __restrict__ b2) {
    int gw = blockIdx.x * 8 + (threadIdx.x >> 5);
    int j = threadIdx.x & 31;
    int q = gw >> 8, p = gw & 255;
    const float* qe = g_emb + q * H1;
    const float* pe = g_emb + (BQ + p) * H1;
    float acc = b1[j];
#pragma unroll 4
    for (int i = 0; i < 256; i++) acc += fmaxf(qe[i], 0.f) * g_w1T[i * 32 + j];
#pragma unroll 4
    for (int i = 0; i < 256; i++) acc += fmaxf(pe[i], 0.f) * g_w1T[(256 + i) * 32 + j];
    float h2 = fmaxf(acc, 0.f);
    float acc3 = b2[j];
#pragma unroll
    for (int m = 0; m < 32; m++) {
        float hm = __shfl_sync(0xffffffffu, h2, m);
        acc3 += hm * g_w2T[m * 32 + j];
    }
    g_h3[gw * 32 + j] = fmaxf(acc3, 0.f);
}

// ================= sparse decode: desc_sim =================
__global__ void k_desc(const float* __restrict__ w3) {
    __shared__ unsigned qm[NW];
    int q = blockIdx.y, pg = blockIdx.x;
    int t = threadIdx.x, lane = t & 31, wid = t >> 5;
    qm[t] = g_mask[q * NW + t];
    __syncthreads();
    int p = pg * 8 + wid;
    const float* h3r = g_h3 + (size_t)(q * 256 + p) * 32;
    float hj[32];
#pragma unroll
    for (int j = 0; j < 32; j++) hj[j] = h3r[j];
    const unsigned* pm = g_mask + (size_t)(BQ + p) * NW;
    float s = 0.f;
    int cnt = 0;
    for (int w8 = 0; w8 < 8; w8++) {
        int wi = w8 * 32 + lane;
        unsigned m = qm[wi] & pm[wi];
        cnt += __popc(m);
        while (m) {
            int b = __ffs(m) - 1;
            m &= m - 1;
            int c = wi * 32 + b;
            const float4* r4 = (const float4*)(w3 + (size_t)c * 32);
            float wv = 0.f;
#pragma unroll
            for (int j4 = 0; j4 < 8; j4++) {
                float4 v = r4[j4];
                wv += hj[j4*4] * v.x + hj[j4*4+1] * v.y + hj[j4*4+2] * v.z + hj[j4*4+3] * v.w;
            }
            s += (wv >= 0.f) ? wv : wv * 0.125f;
        }
    }
#pragma unroll
    for (int off = 16; off; off >>= 1) {
        s += __shfl_down_sync(0xffffffffu, s, off);
        cnt += __shfl_down_sync(0xffffffffu, cnt, off);
    }
    if (lane == 0) g_desc[q * 256 + p] = ((float)cnt + s) / g_qbits[q];
}

// ================= normalization + geo fusion =================
__global__ void k_final(const float* __restrict__ qloc, const float* __restrict__ ploc,
                        const float* __restrict__ pa, const float* __restrict__ pb,
                        const float* __restrict__ pc, const float* __restrict__ pd,
                        float* __restrict__ out) {
    __shared__ float red[256];
    int q = blockIdx.x, p = threadIdx.x;
    float ds = g_desc[q * 256 + p];
    red[p] = ds;
    __syncthreads();
    for (int s = 128; s > 0; s >>= 1) {
        if (p < s) red[p] += red[p + s];
        __syncthreads();
    }
    float mean = red[0] / 256.f;
    __syncthreads();
    float df = ds - mean;
    red[p] = df * df;
    __syncthreads();
    for (int s = 128; s > 0; s >>= 1) {
        if (p < s) red[p] += red[p + s];
        __syncthreads();
    }
    float stddev = sqrtf(red[0] / 255.f);
    float dsn = df / (stddev + 1e-6f);
    float dx = qloc[q * 2] - ploc[p * 2];
    float dy = qloc[q * 2 + 1] - ploc[p * 2 + 1];
    float dist = sqrtf(dx * dx + dy * dy);
    float A = *pa, B = *pb, Cc = *pc, D = *pd;
    float sig = 1.f / (1.f + expf(-(A * dsn + B)));
    out[q * 256 + p] = (Cc - sig) * (-logf(dist + 1.f) - D);
}

// ================= launch =================
extern "C" void kernel_launch(void* const* d_in, const int* in_sizes, int n_in,
                              void* d_out, int out_size) {
    const float* query_x  = (const float*)d_in[0];
    const float* query_loc = (const float*)d_in[1];
    const float* poi_x    = (const float*)d_in[2];
    const float* poi_loc  = (const float*)d_in[3];
    const float* enc_w    = (const float*)d_in[4];
    const float* cw1 = (const float*)d_in[5];  const float* cb1 = (const float*)d_in[6];
    const float* cw2 = (const float*)d_in[7];  const float* cb2 = (const float*)d_in[8];
    const float* cw3 = (const float*)d_in[9];  const float* cb3 = (const float*)d_in[10];
    const float* dw1 = (const float*)d_in[11]; const float* db1 = (const float*)d_in[12];
    const float* dw2 = (const float*)d_in[13]; const float* db2 = (const float*)d_in[14];
    const float* dw3 = (const float*)d_in[15];
    const float* pa = (const float*)d_in[16];
    const float* pb = (const float*)d_in[17];
    const float* pc = (const float*)d_in[18];
    const float* pd = (const float*)d_in[19];
    float* out = (float*)d_out;

    float *p_encT, *p_out3;
    __half *p_wH, *p_wL, *p_hAH, *p_hAL, *p_hBH, *p_hBL;
    cudaGetSymbolAddress((void**)&p_encT, g_encT);
    cudaGetSymbolAddress((void**)&p_wH, g_wH);
    cudaGetSymbolAddress((void**)&p_wL, g_wL);
    cudaGetSymbolAddress((void**)&p_hAH, g_hAH);
    cudaGetSymbolAddress((void**)&p_hAL, g_hAL);
    cudaGetSymbolAddress((void**)&p_hBH, g_hBH);
    cudaGetSymbolAddress((void**)&p_hBL, g_hBL);
    cudaGetSymbolAddress((void**)&p_out3, g_out3);

    cudaFuncSetAttribute(k_conv_mma, cudaFuncAttributeMaxDynamicSharedMemorySize, CONV_SMEM);

    // prep
    k_prep1<<<(NB * LP * H1 / 2 + 255) / 256, 256>>>(dw1, dw2);
    k_prep2<<<(3 * H1 * KTOT + 255) / 256, 256>>>(cw1, cw2, cw3);
    k_transpose<<<dim3(CIN / 32, H1 / 32), dim3(32, 8)>>>(enc_w, p_encT, H1, CIN);
    // encode + blooms
    k_encode<<<dim3(NB, L), 256>>>(query_x, poi_x);
    // conv stack via mma.sync fp16 split-precision
    dim3 cgrid(NB * L / 64, 2);
    k_conv_mma<<<cgrid, 256, CONV_SMEM>>>(p_hAH, p_hAL, p_wH, p_wL, cb1,
                                          p_hBH, p_hBL, (float*)0);
    k_conv_mma<<<cgrid, 256, CONV_SMEM>>>(p_hBH, p_hBL, p_wH + H1 * KTOT, p_wL + H1 * KTOT,
                                          cb2, p_hAH, p_hAL, (float*)0);
    k_conv_mma<<<cgrid, 256, CONV_SMEM>>>(p_hAH, p_hAL, p_wH + 2 * H1 * KTOT, p_wL + 2 * H1 * KTOT,
                                          cb3, (__half*)0, (__half*)0, p_out3);
    // tail
    k_qbits<<<BQ, 256>>>();
    k_emb<<<NB, 256>>>();
    k_pair<<<BQ * BP / 8, 256>>>(db1, db2);
    k_desc<<<dim3(32, 32), 256>>>(dw3);
    k_final<<<BQ, 256>>>(query_loc, poi_loc, pa, pb, pc, pd, out);
}